// round 1
// baseline (speedup 1.0000x reference)
#include <cuda_runtime.h>
#include <math.h>

// Problem constants
#define BB 8
#define SS 2048
#define NNB 16
#define EE 256
#define HH 256
#define MM (BB * SS)      // 16384 tokens
#define G4 (4 * HH)       // 1024 gate width

// GEMM tiling
#define BM 128
#define BN 128
#define BK 16

// Scratch (device globals — no allocation allowed)
__device__ float g_agg[MM * HH];      // masked neighbor sum       (16 MB)
__device__ float g_hn[MM * HH];       // hn = agg @ Wn_a / 16      (16 MB)
__device__ float g_gates[MM * G4];    // pre-activation gates      (64 MB)
__device__ float g_gbias[BB * G4];    // g @ V + Vb                (32 KB)

// ---------------------------------------------------------------------------
// Kernel 1: per-batch gate bias  gbias[b,n] = sum_k g[b,k] * V[k,n] + Vb[n]
// grid (BB, 4), 256 threads
// ---------------------------------------------------------------------------
__global__ void gbias_kernel(const float* __restrict__ g,
                             const float* __restrict__ V,
                             const float* __restrict__ Vb) {
    __shared__ float gs[HH];
    int b = blockIdx.x;
    int t = threadIdx.x;
    gs[t] = g[b * HH + t];
    __syncthreads();
    int n = blockIdx.y * 256 + t;
    float acc = Vb[n];
    #pragma unroll 4
    for (int k = 0; k < HH; ++k) acc += gs[k] * V[k * G4 + n];
    g_gbias[b * G4 + n] = acc;
}

// ---------------------------------------------------------------------------
// Kernel 2: masked neighbor gather-sum.
// 64 threads per token (one float4 lane each), 4 tokens per 256-thread block.
// agg[m,:] = sum_n mask[m,n] * (idx==0 ? 0 : h[b, idx-1, :])
// ---------------------------------------------------------------------------
__global__ void gather_kernel(const float* __restrict__ h,
                              const int* __restrict__ idx,
                              const int* __restrict__ mask) {
    int tid = blockIdx.x * blockDim.x + threadIdx.x;
    int token = tid >> 6;
    int lane = tid & 63;          // float4 index within H=256
    if (token >= MM) return;
    int b = token >> 11;          // S = 2048
    const int* ip = idx + token * NNB;
    const int* mp = mask + token * NNB;
    const float* hb = h + (size_t)b * SS * HH;
    float4 acc = make_float4(0.f, 0.f, 0.f, 0.f);
    #pragma unroll
    for (int n = 0; n < NNB; ++n) {
        int id = ip[n];
        int mk = mp[n];
        if (mk != 0 && id > 0) {
            const float4 v =
                *(const float4*)(hb + (size_t)(id - 1) * HH + lane * 4);
            acc.x += v.x; acc.y += v.y; acc.z += v.z; acc.w += v.w;
        }
    }
    *(float4*)(g_agg + (size_t)token * HH + lane * 4) = acc;
}

// ---------------------------------------------------------------------------
// Kernel 3/4: tiled fp32 GEMM, 128x128 tile, 8x8 per-thread, BK=16.
// MODE 0:  g_hn    = g_agg @ Wn_a * (1/16)                 (N = 256)
// MODE 1:  g_gates = h@Wh + x@U + g_hn@Wn + g_gbias[b]     (N = 1024)
// A row-major (lda=256), B row-major (ldb=N). M,N,K all tile-divisible.
// ---------------------------------------------------------------------------
template <int MODE>
__global__ __launch_bounds__(256) void gemm_kernel(
    const float* __restrict__ A0, const float* __restrict__ A1,
    const float* __restrict__ B0, const float* __restrict__ B1,
    const float* __restrict__ B2) {
    constexpr int N = (MODE == 0) ? HH : G4;
    constexpr int NP = (MODE == 0) ? 1 : 3;
    constexpr float alpha = (MODE == 0) ? (1.0f / 16.0f) : 1.0f;

    __shared__ float As[BK * BM];
    __shared__ float Bs[BK * BN];

    const int tid = threadIdx.x;
    const int bm = blockIdx.y * BM;
    const int bn = blockIdx.x * BN;

    const float* Ap[3];
    const float* Bp[3];
    if (MODE == 0) {
        Ap[0] = g_agg; Bp[0] = B0;
    } else {
        Ap[0] = A0; Ap[1] = A1; Ap[2] = g_hn;
        Bp[0] = B0; Bp[1] = B1; Bp[2] = B2;
    }
    float* C = (MODE == 0) ? g_hn : g_gates;

    float acc[8][8];
    #pragma unroll
    for (int i = 0; i < 8; ++i)
        #pragma unroll
        for (int j = 0; j < 8; ++j) acc[i][j] = 0.f;

    const int arow = tid >> 2;         // 0..63
    const int acol = (tid & 3) * 4;    // 0,4,8,12
    const int brow = tid >> 5;         // 0..7
    const int bcol = (tid & 31) * 4;   // 0..124
    const int ty = tid >> 4;           // 0..15
    const int tx = tid & 15;           // 0..15

    #pragma unroll 1
    for (int p = 0; p < NP; ++p) {
        const float* A = Ap[p];
        const float* B = Bp[p];
        #pragma unroll 1
        for (int k0 = 0; k0 < 256; k0 += BK) {
            __syncthreads();
            // A tile -> As[k][m] (transposed store)
            #pragma unroll
            for (int r = 0; r < 2; ++r) {
                int m = arow + 64 * r;
                float4 v = *(const float4*)(A + (size_t)(bm + m) * 256 + k0 + acol);
                As[(acol + 0) * BM + m] = v.x;
                As[(acol + 1) * BM + m] = v.y;
                As[(acol + 2) * BM + m] = v.z;
                As[(acol + 3) * BM + m] = v.w;
            }
            // B tile -> Bs[k][n]
            #pragma unroll
            for (int r = 0; r < 2; ++r) {
                int k = brow + 8 * r;
                *(float4*)(Bs + k * BN + bcol) =
                    *(const float4*)(B + (size_t)(k0 + k) * N + bn + bcol);
            }
            __syncthreads();
            #pragma unroll
            for (int kk = 0; kk < BK; ++kk) {
                float a[8], bv[8];
                *(float4*)(a)      = *(const float4*)(As + kk * BM + ty * 8);
                *(float4*)(a + 4)  = *(const float4*)(As + kk * BM + ty * 8 + 4);
                *(float4*)(bv)     = *(const float4*)(Bs + kk * BN + tx * 8);
                *(float4*)(bv + 4) = *(const float4*)(Bs + kk * BN + tx * 8 + 4);
                #pragma unroll
                for (int i = 0; i < 8; ++i)
                    #pragma unroll
                    for (int j = 0; j < 8; ++j)
                        acc[i][j] += a[i] * bv[j];
            }
        }
    }

    // Epilogue
    #pragma unroll
    for (int i = 0; i < 8; ++i) {
        int m = bm + ty * 8 + i;
        int bi = m >> 11;  // batch index (S=2048)
        #pragma unroll
        for (int j0 = 0; j0 < 8; j0 += 4) {
            int n = bn + tx * 8 + j0;
            float4 v;
            v.x = acc[i][j0 + 0] * alpha;
            v.y = acc[i][j0 + 1] * alpha;
            v.z = acc[i][j0 + 2] * alpha;
            v.w = acc[i][j0 + 3] * alpha;
            if (MODE == 1) {
                v.x += g_gbias[bi * G4 + n + 0];
                v.y += g_gbias[bi * G4 + n + 1];
                v.z += g_gbias[bi * G4 + n + 2];
                v.w += g_gbias[bi * G4 + n + 3];
            }
            *(float4*)(C + (size_t)m * N + n) = v;
        }
    }
}

// ---------------------------------------------------------------------------
// Kernel 5: LSTM elementwise epilogue.
// out[0 : MM*HH)        = new_h
// out[MM*HH : 2*MM*HH)  = new_c
// ---------------------------------------------------------------------------
__device__ __forceinline__ float sigmoidf_(float x) {
    return 1.0f / (1.0f + expf(-x));
}

__global__ void lstm_kernel(const float* __restrict__ c, float* __restrict__ out) {
    int t = blockIdx.x * blockDim.x + threadIdx.x;  // over MM*64 float4 lanes
    if (t >= MM * 64) return;
    int m = t >> 6;
    int n = (t & 63) * 4;
    const float* gp = g_gates + (size_t)m * G4;
    float4 iv = *(const float4*)(gp + n);
    float4 fv = *(const float4*)(gp + 256 + n);
    float4 ov = *(const float4*)(gp + 512 + n);
    float4 uv = *(const float4*)(gp + 768 + n);
    float4 cv = *(const float4*)(c + (size_t)m * HH + n);

    float4 nc, nh;
    nc.x = sigmoidf_(fv.x) * cv.x + sigmoidf_(iv.x) * tanhf(uv.x);
    nc.y = sigmoidf_(fv.y) * cv.y + sigmoidf_(iv.y) * tanhf(uv.y);
    nc.z = sigmoidf_(fv.z) * cv.z + sigmoidf_(iv.z) * tanhf(uv.z);
    nc.w = sigmoidf_(fv.w) * cv.w + sigmoidf_(iv.w) * tanhf(uv.w);
    nh.x = sigmoidf_(ov.x) * tanhf(nc.x);
    nh.y = sigmoidf_(ov.y) * tanhf(nc.y);
    nh.z = sigmoidf_(ov.z) * tanhf(nc.z);
    nh.w = sigmoidf_(ov.w) * tanhf(nc.w);

    *(float4*)(out + (size_t)m * HH + n) = nh;
    *(float4*)(out + (size_t)MM * HH + (size_t)m * HH + n) = nc;
}

// ---------------------------------------------------------------------------
extern "C" void kernel_launch(void* const* d_in, const int* in_sizes, int n_in,
                              void* d_out, int out_size) {
    const float* x    = (const float*)d_in[0];
    const float* h    = (const float*)d_in[1];
    const float* c    = (const float*)d_in[2];
    const float* g    = (const float*)d_in[3];
    const int*   idx  = (const int*)d_in[4];
    const int*   mask = (const int*)d_in[5];
    // d_in[6]  = Wh_a  (unused: softmax is exactly uniform in fp32)
    const float* Wn_a = (const float*)d_in[7];
    // d_in[8]  = U_a, d_in[9] = u_w, d_in[10] = u_b, d_in[11] = V_a,
    // d_in[12] = Vb_a  (all unused for the same reason)
    const float* Wh   = (const float*)d_in[13];
    const float* Wn   = (const float*)d_in[14];
    const float* U    = (const float*)d_in[15];
    const float* V    = (const float*)d_in[16];
    const float* Vb   = (const float*)d_in[17];
    float* out = (float*)d_out;

    // 1. per-batch gate bias
    gbias_kernel<<<dim3(BB, 4), 256>>>(g, V, Vb);
    // 2. masked neighbor gather-sum
    gather_kernel<<<(MM * 64) / 256, 256>>>(h, idx, mask);
    // 3. hn = agg @ Wn_a / 16
    gemm_kernel<0><<<dim3(HH / BN, MM / BM), 256>>>(nullptr, nullptr, Wn_a,
                                                    nullptr, nullptr);
    // 4. gates = h@Wh + x@U + hn@Wn + gbias
    gemm_kernel<1><<<dim3(G4 / BN, MM / BM), 256>>>(h, x, Wh, U, Wn);
    // 5. LSTM epilogue -> (new_h, new_c)
    lstm_kernel<<<(MM * 64) / 256, 256>>>(c, out);
}

// round 12
// speedup vs baseline: 1.0195x; 1.0195x over previous
#include <cuda_runtime.h>
#include <math.h>

// Problem constants
#define BB 8
#define SS 2048
#define NNB 16
#define EE 256
#define HH 256
#define MM (BB * SS)      // 16384 tokens
#define G4 (4 * HH)       // 1024 gate width

// GEMM tiling
#define BM 128
#define BN 128
#define BK 16

// Scratch (device globals; referenced ONLY from device code — never passed
// as kernel arguments from host, which would bind the host shadow symbol)
__device__ float g_agg[MM * HH];      // masked neighbor sum       (16 MB)
__device__ float g_hn[MM * HH];       // hn = agg @ Wn_a / 16      (16 MB)
__device__ float g_gates[MM * G4];    // pre-activation gates      (64 MB)
__device__ float g_gbias[BB * G4];    // g @ V + Vb                (32 KB)

// ---------------------------------------------------------------------------
// Kernel 1: per-batch gate bias  gbias[b,n] = sum_k g[b,k] * V[k,n] + Vb[n]
// ---------------------------------------------------------------------------
__global__ void gbias_kernel(const float* __restrict__ g,
                             const float* __restrict__ V,
                             const float* __restrict__ Vb) {
    __shared__ float gs[HH];
    int b = blockIdx.x;
    int t = threadIdx.x;
    gs[t] = g[b * HH + t];
    __syncthreads();
    int n = blockIdx.y * 256 + t;
    float acc = Vb[n];
    #pragma unroll 4
    for (int k = 0; k < HH; ++k) acc += gs[k] * V[k * G4 + n];
    g_gbias[b * G4 + n] = acc;
}

// ---------------------------------------------------------------------------
// Kernel 2: masked neighbor gather-sum (softmax over logits*1e-25 is exactly
// uniform in fp32, so attention = (1/16) * sum of masked neighbors @ Wn_a).
// ---------------------------------------------------------------------------
__global__ void gather_kernel(const float* __restrict__ h,
                              const int* __restrict__ idx,
                              const int* __restrict__ mask) {
    int tid = blockIdx.x * blockDim.x + threadIdx.x;
    int token = tid >> 6;
    int lane = tid & 63;          // float4 index within H=256
    if (token >= MM) return;
    int b = token >> 11;          // S = 2048
    const int* ip = idx + token * NNB;
    const int* mp = mask + token * NNB;
    const float* hb = h + (size_t)b * SS * HH;
    float4 acc = make_float4(0.f, 0.f, 0.f, 0.f);
    #pragma unroll
    for (int n = 0; n < NNB; ++n) {
        int id = ip[n];
        int mk = mp[n];
        if (mk != 0 && id > 0) {
            const float4 v =
                *(const float4*)(hb + (size_t)(id - 1) * HH + lane * 4);
            acc.x += v.x; acc.y += v.y; acc.z += v.z; acc.w += v.w;
        }
    }
    *(float4*)(g_agg + (size_t)token * HH + lane * 4) = acc;
}

// ---------------------------------------------------------------------------
// Kernel 3/4: tiled fp32 GEMM, 128x128 tile, 8x8 per-thread, BK=16,
// software-pipelined: register prefetch of the next K-chunk overlapped with
// compute, double-buffered smem, ONE __syncthreads per chunk.
// MODE 0:  g_hn    = g_agg @ Wn_a * (1/16)                 (N = 256)
// MODE 1:  g_gates = h@Wh + x@U + g_hn@Wn + g_gbias[b]     (N = 1024)
// A row-major (lda=256), B row-major (ldb=N). All device-scratch pointers are
// bound inside device code.
// ---------------------------------------------------------------------------
template <int MODE>
__global__ __launch_bounds__(256, 2) void gemm_kernel(
    const float* __restrict__ A0, const float* __restrict__ A1,
    const float* __restrict__ B0, const float* __restrict__ B1,
    const float* __restrict__ B2) {
    constexpr int N = (MODE == 0) ? HH : G4;
    constexpr int NCHUNK = (MODE == 0) ? 16 : 48;   // K=256 per pair, BK=16
    constexpr float alpha = (MODE == 0) ? (1.0f / 16.0f) : 1.0f;

    __shared__ float As[2][BK][BM];
    __shared__ float Bs[2][BK][BN];

    const int tid = threadIdx.x;
    const int bm = blockIdx.y * BM;
    const int bn = blockIdx.x * BN;

    const int arow = tid >> 2;         // 0..63
    const int acol = (tid & 3) * 4;    // 0,4,8,12
    const int brow = tid >> 5;         // 0..7
    const int bcol = (tid & 31) * 4;   // 0..124
    const int ty = tid >> 4;           // 0..15
    const int tx = tid & 15;           // 0..15

    float acc[8][8];
    #pragma unroll
    for (int i = 0; i < 8; ++i)
        #pragma unroll
        for (int j = 0; j < 8; ++j) acc[i][j] = 0.f;

    float4 pa0, pa1, pb0, pb1;

    // chunk c: MODE1 pair p = c/16 selects (h,Wh), (x,U), (g_hn,Wn);
    // MODE0 always (g_agg, Wn_a). k0 = (c&15)*16.
#define FETCH_CHUNK(c)                                                         \
    {                                                                          \
        const float* A_;                                                       \
        const float* B_;                                                       \
        if (MODE == 0) { A_ = g_agg; B_ = B0; }                                \
        else {                                                                 \
            A_ = ((c) < 16) ? A0 : ((c) < 32) ? A1 : g_hn;                     \
            B_ = ((c) < 16) ? B0 : ((c) < 32) ? B1 : B2;                       \
        }                                                                      \
        const int k0_ = ((c) & 15) * 16;                                       \
        pa0 = *(const float4*)(A_ + (size_t)(bm + arow) * 256 + k0_ + acol);   \
        pa1 = *(const float4*)(A_ + (size_t)(bm + arow + 64) * 256 + k0_ + acol); \
        pb0 = *(const float4*)(B_ + (size_t)(k0_ + brow) * N + bn + bcol);     \
        pb1 = *(const float4*)(B_ + (size_t)(k0_ + brow + 8) * N + bn + bcol); \
    }

#define STORE_CHUNK(s)                                                         \
    {                                                                          \
        As[s][acol + 0][arow] = pa0.x;                                         \
        As[s][acol + 1][arow] = pa0.y;                                         \
        As[s][acol + 2][arow] = pa0.z;                                         \
        As[s][acol + 3][arow] = pa0.w;                                         \
        As[s][acol + 0][arow + 64] = pa1.x;                                    \
        As[s][acol + 1][arow + 64] = pa1.y;                                    \
        As[s][acol + 2][arow + 64] = pa1.z;                                    \
        As[s][acol + 3][arow + 64] = pa1.w;                                    \
        *(float4*)(&Bs[s][brow][bcol]) = pb0;                                  \
        *(float4*)(&Bs[s][brow + 8][bcol]) = pb1;                              \
    }

    // prologue: chunk 0 into buffer 0
    FETCH_CHUNK(0);
    STORE_CHUNK(0);
    __syncthreads();

    #pragma unroll 1
    for (int c = 0; c < NCHUNK; ++c) {
        const int s = c & 1;
        if (c + 1 < NCHUNK) FETCH_CHUNK(c + 1);   // LDG in flight over compute

        #pragma unroll
        for (int kk = 0; kk < BK; ++kk) {
            float a[8], bv[8];
            *(float4*)(a)      = *(const float4*)(&As[s][kk][ty * 8]);
            *(float4*)(a + 4)  = *(const float4*)(&As[s][kk][ty * 8 + 4]);
            *(float4*)(bv)     = *(const float4*)(&Bs[s][kk][tx * 8]);
            *(float4*)(bv + 4) = *(const float4*)(&Bs[s][kk][tx * 8 + 4]);
            #pragma unroll
            for (int i = 0; i < 8; ++i)
                #pragma unroll
                for (int j = 0; j < 8; ++j)
                    acc[i][j] += a[i] * bv[j];
        }

        if (c + 1 < NCHUNK) {
            STORE_CHUNK(s ^ 1);   // buffer s^1 finished being read at iter c-1
        }
        __syncthreads();
    }

#undef FETCH_CHUNK
#undef STORE_CHUNK

    // -------- epilogue --------
    #pragma unroll
    for (int i = 0; i < 8; ++i) {
        int m = bm + ty * 8 + i;
        int bi = m >> 11;  // batch index (S=2048)
        #pragma unroll
        for (int j0 = 0; j0 < 8; j0 += 4) {
            int n = bn + tx * 8 + j0;
            float4 v;
            v.x = acc[i][j0 + 0] * alpha;
            v.y = acc[i][j0 + 1] * alpha;
            v.z = acc[i][j0 + 2] * alpha;
            v.w = acc[i][j0 + 3] * alpha;
            if (MODE == 1) {
                v.x += g_gbias[bi * G4 + n + 0];
                v.y += g_gbias[bi * G4 + n + 1];
                v.z += g_gbias[bi * G4 + n + 2];
                v.w += g_gbias[bi * G4 + n + 3];
                *(float4*)(g_gates + (size_t)m * G4 + n) = v;
            } else {
                *(float4*)(g_hn + (size_t)m * HH + n) = v;
            }
        }
    }
}

// ---------------------------------------------------------------------------
// Kernel 5: LSTM elementwise epilogue.
// out[0 : MM*HH) = new_h ; out[MM*HH : 2*MM*HH) = new_c
// ---------------------------------------------------------------------------
__device__ __forceinline__ float sigmoidf_(float x) {
    return 1.0f / (1.0f + expf(-x));
}

__global__ void lstm_kernel(const float* __restrict__ c, float* __restrict__ out) {
    int t = blockIdx.x * blockDim.x + threadIdx.x;  // over MM*64 float4 lanes
    if (t >= MM * 64) return;
    int m = t >> 6;
    int n = (t & 63) * 4;
    const float* gp = g_gates + (size_t)m * G4;
    float4 iv = *(const float4*)(gp + n);
    float4 fv = *(const float4*)(gp + 256 + n);
    float4 ov = *(const float4*)(gp + 512 + n);
    float4 uv = *(const float4*)(gp + 768 + n);
    float4 cv = *(const float4*)(c + (size_t)m * HH + n);

    float4 nc, nh;
    nc.x = sigmoidf_(fv.x) * cv.x + sigmoidf_(iv.x) * tanhf(uv.x);
    nc.y = sigmoidf_(fv.y) * cv.y + sigmoidf_(iv.y) * tanhf(uv.y);
    nc.z = sigmoidf_(fv.z) * cv.z + sigmoidf_(iv.z) * tanhf(uv.z);
    nc.w = sigmoidf_(fv.w) * cv.w + sigmoidf_(iv.w) * tanhf(uv.w);
    nh.x = sigmoidf_(ov.x) * tanhf(nc.x);
    nh.y = sigmoidf_(ov.y) * tanhf(nc.y);
    nh.z = sigmoidf_(ov.z) * tanhf(nc.z);
    nh.w = sigmoidf_(ov.w) * tanhf(nc.w);

    *(float4*)(out + (size_t)m * HH + n) = nh;
    *(float4*)(out + (size_t)MM * HH + (size_t)m * HH + n) = nc;
}

// ---------------------------------------------------------------------------
extern "C" void kernel_launch(void* const* d_in, const int* in_sizes, int n_in,
                              void* d_out, int out_size) {
    const float* x    = (const float*)d_in[0];
    const float* h    = (const float*)d_in[1];
    const float* c    = (const float*)d_in[2];
    const float* g    = (const float*)d_in[3];
    const int*   idx  = (const int*)d_in[4];
    const int*   mask = (const int*)d_in[5];
    // d_in[6] Wh_a, d_in[8] U_a, d_in[9] u_w, d_in[10] u_b, d_in[11] V_a,
    // d_in[12] Vb_a: unused — softmax over logits*1e-25 is exactly uniform in fp32.
    const float* Wn_a = (const float*)d_in[7];
    const float* Wh   = (const float*)d_in[13];
    const float* Wn   = (const float*)d_in[14];
    const float* U    = (const float*)d_in[15];
    const float* V    = (const float*)d_in[16];
    const float* Vb   = (const float*)d_in[17];
    float* out = (float*)d_out;

    // 1. per-batch gate bias
    gbias_kernel<<<dim3(BB, 4), 256>>>(g, V, Vb);
    // 2. masked neighbor gather-sum
    gather_kernel<<<(MM * 64) / 256, 256>>>(h, idx, mask);
    // 3. hn = agg @ Wn_a / 16   (M=16384, N=256, K=256); scratch bound device-side
    gemm_kernel<0><<<dim3(HH / BN, MM / BM), 256>>>(nullptr, nullptr, Wn_a,
                                                    nullptr, nullptr);
    // 4. gates = h@Wh + x@U + hn@Wn + gbias   (M=16384, N=1024, K=768)
    gemm_kernel<1><<<dim3(G4 / BN, MM / BM), 256>>>(h, x, Wh, U, Wn);
    // 5. LSTM epilogue -> (new_h, new_c)
    lstm_kernel<<<(MM * 64) / 256, 256>>>(c, out);
}

// round 13
// speedup vs baseline: 2.1604x; 2.1191x over previous
#include <cuda_runtime.h>
#include <cuda_bf16.h>
#include <cstdint>
#include <math.h>

// ---------------------------------------------------------------- constants
#define BB 8
#define SS 2048
#define NNB 16
#define HH 256
#define MM (BB * SS)          // 16384 tokens
#define G4 (4 * HH)           // 1024
#define K2 768                // fused K for gates GEMM

// -------- scratch: device globals, referenced ONLY from device code --------
__device__ float g_gbias[BB * G4];                  // permuted layout
__device__ __nv_bfloat16 g_A2hi[(size_t)MM * K2];   // [h | x | hn] hi
__device__ __nv_bfloat16 g_A2lo[(size_t)MM * K2];   // [h | x | hn] lo
__device__ __nv_bfloat16 g_B2hi[G4 * K2];           // perm([Wh;U;Wn]^T) hi
__device__ __nv_bfloat16 g_B2lo[G4 * K2];
__device__ __nv_bfloat16 g_B1hi[HH * HH];           // Wn_a^T hi (n-major)
__device__ __nv_bfloat16 g_B1lo[HH * HH];
__device__ __nv_bfloat16 g_AGhi[(size_t)MM * HH];   // neighbor agg hi
__device__ __nv_bfloat16 g_AGlo[(size_t)MM * HH];

// ---------------------------------------------------------------- PTX utils
__device__ __forceinline__ uint32_t smem_u32(const void* p) {
    uint32_t a;
    asm("{ .reg .u64 t; cvta.to.shared.u64 t, %1; cvt.u32.u64 %0, t; }"
        : "=r"(a) : "l"(p));
    return a;
}
__device__ __forceinline__ void cp_async16(uint32_t dst, const void* src) {
    asm volatile("cp.async.cg.shared.global [%0], [%1], 16;"
                 :: "r"(dst), "l"(src) : "memory");
}
__device__ __forceinline__ void cp_commit() {
    asm volatile("cp.async.commit_group;" ::: "memory");
}
template <int N>
__device__ __forceinline__ void cp_wait() {
    asm volatile("cp.async.wait_group %0;" :: "n"(N) : "memory");
}
#define LDSM_X4(r0, r1, r2, r3, addr)                                            \
    asm volatile("ldmatrix.sync.aligned.m8n8.x4.shared.b16 {%0,%1,%2,%3}, [%4];" \
                 : "=r"(r0), "=r"(r1), "=r"(r2), "=r"(r3) : "r"(addr))
#define MMA_BF16(d0, d1, d2, d3, a0, a1, a2, a3, b0, b1)                         \
    asm volatile("mma.sync.aligned.m16n8k16.row.col.f32.bf16.bf16.f32 "          \
                 "{%0,%1,%2,%3}, {%4,%5,%6,%7}, {%8,%9}, {%0,%1,%2,%3};"         \
                 : "+f"(d0), "+f"(d1), "+f"(d2), "+f"(d3)                        \
                 : "r"(a0), "r"(a1), "r"(a2), "r"(a3), "r"(b0), "r"(b1))
#define MMA4(Cn, a0, a1, a2, a3, b0, b1)                                         \
    MMA_BF16(Cn##_0, Cn##_1, Cn##_2, Cn##_3, a0, a1, a2, a3, b0, b1)
#define BF16SPLIT(v, hi, lo)                                                     \
    { hi = __float2bfloat16(v); lo = __float2bfloat16((v) - __bfloat162float(hi)); }

__device__ __forceinline__ float sigmoidf_(float x) {
    return 1.0f / (1.0f + expf(-x));
}

// N permutation for the gates GEMM (thread-local i/f/o/u grouping):
// n = q*256 + idx; blk = idx>>5; lh = idx&31
// n' = blk*128 + (lh>>4)*64 + (q + 4*((lh>>3)&1))*8 + (lh&7)
__device__ __forceinline__ int perm_n(int n) {
    int q = n >> 8, idx = n & 255;
    int lh = idx & 31;
    return (idx >> 5) * 128 + (lh >> 4) * 64 + ((q + 4 * ((lh >> 3) & 1)) << 3) +
           (lh & 7);
}

// ---------------------------------------------------------------- gbias (permuted)
__global__ void gbias_kernel(const float* __restrict__ g,
                             const float* __restrict__ V,
                             const float* __restrict__ Vb) {
    __shared__ float gs[HH];
    int b = blockIdx.x, t = threadIdx.x;
    gs[t] = g[b * HH + t];
    __syncthreads();
    int n = blockIdx.y * 256 + t;
    float acc = Vb[n];
    #pragma unroll 4
    for (int k = 0; k < HH; ++k) acc += gs[k] * V[k * G4 + n];
    g_gbias[b * G4 + perm_n(n)] = acc;
}

// ---------------------------------------------------------------- converts
__global__ void conv_A(const float* __restrict__ h, const float* __restrict__ x) {
    int t = blockIdx.x * 256 + threadIdx.x;   // MM*128 threads
    int m = t >> 7;
    int c = (t & 127) * 4;                    // 0..508
    const float* src = (c < 256) ? (h + (size_t)m * HH + c)
                                 : (x + (size_t)m * HH + (c - 256));
    float4 v = *(const float4*)src;
    size_t o = (size_t)m * K2 + c;
    __nv_bfloat16 h0, l0, h1, l1, h2, l2, h3, l3;
    BF16SPLIT(v.x, h0, l0); BF16SPLIT(v.y, h1, l1);
    BF16SPLIT(v.z, h2, l2); BF16SPLIT(v.w, h3, l3);
    *(__nv_bfloat162*)(g_A2hi + o)     = __halves2bfloat162(h0, h1);
    *(__nv_bfloat162*)(g_A2hi + o + 2) = __halves2bfloat162(h2, h3);
    *(__nv_bfloat162*)(g_A2lo + o)     = __halves2bfloat162(l0, l1);
    *(__nv_bfloat162*)(g_A2lo + o + 2) = __halves2bfloat162(l2, l3);
}

__global__ void conv_B(const float* __restrict__ Wh, const float* __restrict__ U,
                       const float* __restrict__ Wn, const float* __restrict__ Wn_a) {
    int t = blockIdx.x * 256 + threadIdx.x;
    if (t < G4 * K2) {
        int k = t >> 10, n = t & 1023;
        float v = (k < 256) ? Wh[(size_t)k * G4 + n]
                : (k < 512) ? U[(size_t)(k - 256) * G4 + n]
                            : Wn[(size_t)(k - 512) * G4 + n];
        __nv_bfloat16 hi, lo;
        BF16SPLIT(v, hi, lo);
        size_t np = (size_t)perm_n(n);
        g_B2hi[np * K2 + k] = hi;
        g_B2lo[np * K2 + k] = lo;
    } else {
        int t2 = t - G4 * K2;
        if (t2 < HH * HH) {
            int k = t2 >> 8, n = t2 & 255;
            float v = Wn_a[k * HH + n];
            __nv_bfloat16 hi, lo;
            BF16SPLIT(v, hi, lo);
            g_B1hi[n * HH + k] = hi;
            g_B1lo[n * HH + k] = lo;
        }
    }
}

// ---------------------------------------------------------------- gather
__global__ void gather_kernel(const float* __restrict__ h,
                              const int* __restrict__ idx,
                              const int* __restrict__ mask) {
    int tid = blockIdx.x * blockDim.x + threadIdx.x;
    int token = tid >> 6;
    int lane = tid & 63;
    if (token >= MM) return;
    int b = token >> 11;
    const int* ip = idx + token * NNB;
    const int* mp = mask + token * NNB;
    const float* hb = h + (size_t)b * SS * HH;
    float4 acc = make_float4(0.f, 0.f, 0.f, 0.f);
    #pragma unroll
    for (int n = 0; n < NNB; ++n) {
        int id = ip[n];
        int mk = mp[n];
        if (mk != 0 && id > 0) {
            const float4 v = *(const float4*)(hb + (size_t)(id - 1) * HH + lane * 4);
            acc.x += v.x; acc.y += v.y; acc.z += v.z; acc.w += v.w;
        }
    }
    size_t o = (size_t)token * HH + lane * 4;
    __nv_bfloat16 h0, l0, h1, l1, h2, l2, h3, l3;
    BF16SPLIT(acc.x, h0, l0); BF16SPLIT(acc.y, h1, l1);
    BF16SPLIT(acc.z, h2, l2); BF16SPLIT(acc.w, h3, l3);
    *(__nv_bfloat162*)(g_AGhi + o)     = __halves2bfloat162(h0, h1);
    *(__nv_bfloat162*)(g_AGhi + o + 2) = __halves2bfloat162(h2, h3);
    *(__nv_bfloat162*)(g_AGlo + o)     = __halves2bfloat162(l0, l1);
    *(__nv_bfloat162*)(g_AGlo + o + 2) = __halves2bfloat162(l2, l3);
}

// ---------------------------------------------------------------- mma GEMM
// 128x128 block, 8 warps (32m x 64n per warp), BK=16, double-buffered cp.async,
// static 32 KB smem, split-bf16: C = Ahi*Bhi + Alo*Bhi + Ahi*Blo.
// Tiles per stage: Ahi(+0) Alo(+4K) Bhi(+8K) Blo(+12K), 128 rows x 32 B,
// swizzle: off = row*32 + (kb ^ ((row&4)<<2)).
#define STG_B 16384

#define DECL4(p) float p##_0 = 0.f, p##_1 = 0.f, p##_2 = 0.f, p##_3 = 0.f

#define BJ_BLOCK(bj, CA0, CA1, CB0, CB1)                                       \
    do {                                                                       \
        int rowb = wn * 64 + (bj) * 16 + (lid & 15);                           \
        uint32_t offb = SB + 8192 + rowb * 32 + (KB ^ ((rowb & 4) << 2));      \
        uint32_t bh0, bh1, bh2, bh3, bl0, bl1, bl2, bl3;                       \
        LDSM_X4(bh0, bh1, bh2, bh3, offb);                                     \
        LDSM_X4(bl0, bl1, bl2, bl3, offb + 4096);                              \
        MMA4(CA0, ah0_0, ah0_1, ah0_2, ah0_3, bh0, bh2);                       \
        MMA4(CA1, ah0_0, ah0_1, ah0_2, ah0_3, bh1, bh3);                       \
        MMA4(CB0, ah1_0, ah1_1, ah1_2, ah1_3, bh0, bh2);                       \
        MMA4(CB1, ah1_0, ah1_1, ah1_2, ah1_3, bh1, bh3);                       \
        MMA4(CA0, al0_0, al0_1, al0_2, al0_3, bh0, bh2);                       \
        MMA4(CA1, al0_0, al0_1, al0_2, al0_3, bh1, bh3);                       \
        MMA4(CB0, al1_0, al1_1, al1_2, al1_3, bh0, bh2);                       \
        MMA4(CB1, al1_0, al1_1, al1_2, al1_3, bh1, bh3);                       \
        MMA4(CA0, ah0_0, ah0_1, ah0_2, ah0_3, bl0, bl2);                       \
        MMA4(CA1, ah0_0, ah0_1, ah0_2, ah0_3, bl1, bl3);                       \
        MMA4(CB0, ah1_0, ah1_1, ah1_2, ah1_3, bl0, bl2);                       \
        MMA4(CB1, ah1_0, ah1_1, ah1_2, ah1_3, bl1, bl3);                       \
    } while (0)

#define HN_ST(Cn, MI, NI)                                                      \
    do {                                                                       \
        int col = bn + wn * 64 + (NI) * 8 + tq * 2;                            \
        int m0 = bm + wm * 32 + (MI) * 16 + quad;                              \
        __nv_bfloat16 p0, q0, p1, q1;                                          \
        float v0 = Cn##_0 * 0.0625f, v1 = Cn##_1 * 0.0625f;                    \
        BF16SPLIT(v0, p0, q0); BF16SPLIT(v1, p1, q1);                          \
        size_t o = (size_t)m0 * K2 + 512 + col;                                \
        *(__nv_bfloat162*)(g_A2hi + o) = __halves2bfloat162(p0, p1);           \
        *(__nv_bfloat162*)(g_A2lo + o) = __halves2bfloat162(q0, q1);           \
        v0 = Cn##_2 * 0.0625f; v1 = Cn##_3 * 0.0625f;                          \
        BF16SPLIT(v0, p0, q0); BF16SPLIT(v1, p1, q1);                          \
        o = (size_t)(m0 + 8) * K2 + 512 + col;                                 \
        *(__nv_bfloat162*)(g_A2hi + o) = __halves2bfloat162(p0, p1);           \
        *(__nv_bfloat162*)(g_A2lo + o) = __halves2bfloat162(q0, q1);           \
    } while (0)

#define LSTM_E(i0, i1, f0, f1, o0, o1, u0, u1, MME, HCE, gI, gF, gO, gU)       \
    do {                                                                       \
        float2 cv = *(const float2*)(cin + (size_t)(MME) * HH + (HCE));        \
        float ivx = (i0) + gI.x, ivy = (i1) + gI.y;                            \
        float fvx = (f0) + gF.x, fvy = (f1) + gF.y;                            \
        float ovx = (o0) + gO.x, ovy = (o1) + gO.y;                            \
        float uvx = (u0) + gU.x, uvy = (u1) + gU.y;                            \
        float ncx = sigmoidf_(fvx) * cv.x + sigmoidf_(ivx) * tanhf(uvx);       \
        float ncy = sigmoidf_(fvy) * cv.y + sigmoidf_(ivy) * tanhf(uvy);       \
        float2 nh = make_float2(sigmoidf_(ovx) * tanhf(ncx),                   \
                                sigmoidf_(ovy) * tanhf(ncy));                  \
        *(float2*)(out + (size_t)(MME) * HH + (HCE)) = nh;                     \
        *(float2*)(out + (size_t)MM * HH + (size_t)(MME) * HH + (HCE)) =       \
            make_float2(ncx, ncy);                                             \
    } while (0)

// MODE0: hn = agg @ Wn_a^T / 16 -> A2 cols 512..767 (bf16 hi/lo), KTOT=256
// MODE1: gates(perm cols) + gbias -> fused LSTM -> out, KTOT=768
// All scratch operand pointers are bound INSIDE device code (host shadow
// symbols must never be passed as kernel args).
template <int MODE>
__global__ __launch_bounds__(256, 1)
void mma_gemm(const float* __restrict__ cin, float* __restrict__ out) {
    constexpr int KTOT = (MODE == 0) ? HH : K2;
    constexpr int NC = KTOT / 16;

    const __nv_bfloat16* __restrict__ A_hi = (MODE == 0) ? g_AGhi : g_A2hi;
    const __nv_bfloat16* __restrict__ A_lo = (MODE == 0) ? g_AGlo : g_A2lo;
    const __nv_bfloat16* __restrict__ B_hi = (MODE == 0) ? g_B1hi : g_B2hi;
    const __nv_bfloat16* __restrict__ B_lo = (MODE == 0) ? g_B1lo : g_B2lo;

    __shared__ __align__(128) char smem_buf[2 * STG_B];
    const uint32_t sb = smem_u32(smem_buf);
    const int tid = threadIdx.x;
    const int wid = tid >> 5, lid = tid & 31;
    const int wm = wid & 3, wn = wid >> 2;       // 4 x 2 warp grid
    const int bm = blockIdx.y * 128, bn = blockIdx.x * 128;

    DECL4(C00); DECL4(C01); DECL4(C02); DECL4(C03);
    DECL4(C04); DECL4(C05); DECL4(C06); DECL4(C07);
    DECL4(C10); DECL4(C11); DECL4(C12); DECL4(C13);
    DECL4(C14); DECL4(C15); DECL4(C16); DECL4(C17);

    // stage loader (device-side pointers only)
    const int lrow = tid >> 1;
    const uint32_t loff = (uint32_t)lrow * 32 +
                          (((uint32_t)(tid & 1) * 16) ^ ((lrow & 4) << 2));
    const int le8 = (tid & 1) * 8;

#define LOAD_STAGE(st, kc)                                                     \
    {                                                                          \
        const int k0_ = (kc) * 16;                                             \
        const uint32_t base_ = sb + (st) * STG_B + loff;                       \
        const size_t ga_ = (size_t)(bm + lrow) * KTOT + k0_ + le8;             \
        const size_t gb_ = (size_t)(bn + lrow) * KTOT + k0_ + le8;             \
        cp_async16(base_, A_hi + ga_);                                         \
        cp_async16(base_ + 4096, A_lo + ga_);                                  \
        cp_async16(base_ + 8192, B_hi + gb_);                                  \
        cp_async16(base_ + 12288, B_lo + gb_);                                 \
    }

    LOAD_STAGE(0, 0);
    cp_commit();

    #pragma unroll 1
    for (int kc = 0; kc < NC; ++kc) {
        if (kc + 1 < NC) {
            LOAD_STAGE((kc + 1) & 1, kc + 1);
            cp_commit();
            cp_wait<1>();
        } else {
            cp_wait<0>();
        }
        __syncthreads();

        const uint32_t SB = sb + (uint32_t)(kc & 1) * STG_B;
        const uint32_t KB = (uint32_t)(lid >> 4) * 16;

        uint32_t ah0_0, ah0_1, ah0_2, ah0_3, ah1_0, ah1_1, ah1_2, ah1_3;
        uint32_t al0_0, al0_1, al0_2, al0_3, al1_0, al1_1, al1_2, al1_3;
        {
            int rowa = wm * 32 + (lid & 15);
            uint32_t offa = SB + rowa * 32 + (KB ^ ((rowa & 4) << 2));
            LDSM_X4(ah0_0, ah0_1, ah0_2, ah0_3, offa);
            LDSM_X4(al0_0, al0_1, al0_2, al0_3, offa + 4096);
            int rowc = rowa + 16;
            uint32_t offc = SB + rowc * 32 + (KB ^ ((rowc & 4) << 2));
            LDSM_X4(ah1_0, ah1_1, ah1_2, ah1_3, offc);
            LDSM_X4(al1_0, al1_1, al1_2, al1_3, offc + 4096);
        }
        BJ_BLOCK(0, C00, C01, C10, C11);
        BJ_BLOCK(1, C02, C03, C12, C13);
        BJ_BLOCK(2, C04, C05, C14, C15);
        BJ_BLOCK(3, C06, C07, C16, C17);
        __syncthreads();
    }
#undef LOAD_STAGE

    // -------- epilogue --------
    const int quad = lid >> 2, tq = lid & 3;

    if (MODE == 0) {
        HN_ST(C00, 0, 0); HN_ST(C01, 0, 1); HN_ST(C02, 0, 2); HN_ST(C03, 0, 3);
        HN_ST(C04, 0, 4); HN_ST(C05, 0, 5); HN_ST(C06, 0, 6); HN_ST(C07, 0, 7);
        HN_ST(C10, 1, 0); HN_ST(C11, 1, 1); HN_ST(C12, 1, 2); HN_ST(C13, 1, 3);
        HN_ST(C14, 1, 4); HN_ST(C15, 1, 5); HN_ST(C16, 1, 6); HN_ST(C17, 1, 7);
    } else {
        const int bi = blockIdx.y >> 4;          // batch (16 m-tiles per batch)
        const float* gbp = g_gbias + bi * G4 + blockIdx.x * 128 + wn * 64 + tq * 2;
        float2 gI0 = *(const float2*)(gbp + 0);
        float2 gF0 = *(const float2*)(gbp + 8);
        float2 gO0 = *(const float2*)(gbp + 16);
        float2 gU0 = *(const float2*)(gbp + 24);
        float2 gI1 = *(const float2*)(gbp + 32);
        float2 gF1 = *(const float2*)(gbp + 40);
        float2 gO1 = *(const float2*)(gbp + 48);
        float2 gU1 = *(const float2*)(gbp + 56);
        const int m0 = bm + wm * 32 + quad;
        const int hc0 = blockIdx.x * 32 + wn * 16 + tq * 2;
        const int hc1 = hc0 + 8;
        // mi=0
        LSTM_E(C00_0, C00_1, C01_0, C01_1, C02_0, C02_1, C03_0, C03_1,
               m0, hc0, gI0, gF0, gO0, gU0);
        LSTM_E(C00_2, C00_3, C01_2, C01_3, C02_2, C02_3, C03_2, C03_3,
               m0 + 8, hc0, gI0, gF0, gO0, gU0);
        LSTM_E(C04_0, C04_1, C05_0, C05_1, C06_0, C06_1, C07_0, C07_1,
               m0, hc1, gI1, gF1, gO1, gU1);
        LSTM_E(C04_2, C04_3, C05_2, C05_3, C06_2, C06_3, C07_2, C07_3,
               m0 + 8, hc1, gI1, gF1, gO1, gU1);
        // mi=1
        LSTM_E(C10_0, C10_1, C11_0, C11_1, C12_0, C12_1, C13_0, C13_1,
               m0 + 16, hc0, gI0, gF0, gO0, gU0);
        LSTM_E(C10_2, C10_3, C11_2, C11_3, C12_2, C12_3, C13_2, C13_3,
               m0 + 24, hc0, gI0, gF0, gO0, gU0);
        LSTM_E(C14_0, C14_1, C15_0, C15_1, C16_0, C16_1, C17_0, C17_1,
               m0 + 16, hc1, gI1, gF1, gO1, gU1);
        LSTM_E(C14_2, C14_3, C15_2, C15_3, C16_2, C16_3, C17_2, C17_3,
               m0 + 24, hc1, gI1, gF1, gO1, gU1);
    }
}

// ----------------------------------------------------------------------------
extern "C" void kernel_launch(void* const* d_in, const int* in_sizes, int n_in,
                              void* d_out, int out_size) {
    const float* x    = (const float*)d_in[0];
    const float* h    = (const float*)d_in[1];
    const float* c    = (const float*)d_in[2];
    const float* g    = (const float*)d_in[3];
    const int*   idx  = (const int*)d_in[4];
    const int*   mask = (const int*)d_in[5];
    // d_in[6] Wh_a, d_in[8..12]: unused — softmax over logits*1e-25 is exactly
    // uniform in fp32, so the attention score is 1/16 for every neighbor.
    const float* Wn_a = (const float*)d_in[7];
    const float* Wh   = (const float*)d_in[13];
    const float* Wn   = (const float*)d_in[14];
    const float* U    = (const float*)d_in[15];
    const float* V    = (const float*)d_in[16];
    const float* Vb   = (const float*)d_in[17];
    float* out = (float*)d_out;

    gbias_kernel<<<dim3(BB, 4), 256>>>(g, V, Vb);
    conv_A<<<(MM * 128) / 256, 256>>>(h, x);
    conv_B<<<(G4 * K2 + HH * HH + 255) / 256, 256>>>(Wh, U, Wn, Wn_a);
    gather_kernel<<<(MM * 64) / 256, 256>>>(h, idx, mask);
    // hn = agg @ Wn_a^T-layout / 16   (M=16384, N=256, K=256)
    mma_gemm<0><<<dim3(2, MM / 128), 256>>>(nullptr, nullptr);
    // gates(+fused LSTM) -> out       (M=16384, N=1024 permuted, K=768)
    mma_gemm<1><<<dim3(8, MM / 128), 256>>>(c, out);
}

// round 14
// speedup vs baseline: 2.2419x; 1.0377x over previous
#include <cuda_runtime.h>
#include <cuda_bf16.h>
#include <cstdint>
#include <math.h>

// ---------------------------------------------------------------- constants
#define BB 8
#define SS 2048
#define NNB 16
#define HH 256
#define MM (BB * SS)          // 16384 tokens
#define G4 (4 * HH)           // 1024
#define K2 768                // fused K for gates GEMM

// -------- scratch: device globals, referenced ONLY from device code --------
__device__ float g_gbias[BB * G4];                  // permuted layout
__device__ __nv_bfloat16 g_A2hi[(size_t)MM * K2];   // [h | x | hn] hi
__device__ __nv_bfloat16 g_A2lo[(size_t)MM * K2];   // [h | x | hn] lo
__device__ __nv_bfloat16 g_B2hi[G4 * K2];           // perm([Wh;U;Wn]^T) hi
__device__ __nv_bfloat16 g_B2lo[G4 * K2];
__device__ __nv_bfloat16 g_B1hi[HH * HH];           // Wn_a^T hi (n-major)
__device__ __nv_bfloat16 g_B1lo[HH * HH];
__device__ __nv_bfloat16 g_AGhi[(size_t)MM * HH];   // neighbor agg hi
__device__ __nv_bfloat16 g_AGlo[(size_t)MM * HH];

// ---------------------------------------------------------------- PTX utils
__device__ __forceinline__ uint32_t smem_u32(const void* p) {
    uint32_t a;
    asm("{ .reg .u64 t; cvta.to.shared.u64 t, %1; cvt.u32.u64 %0, t; }"
        : "=r"(a) : "l"(p));
    return a;
}
__device__ __forceinline__ void cp_async16(uint32_t dst, const void* src) {
    asm volatile("cp.async.cg.shared.global [%0], [%1], 16;"
                 :: "r"(dst), "l"(src) : "memory");
}
__device__ __forceinline__ void cp_commit() {
    asm volatile("cp.async.commit_group;" ::: "memory");
}
template <int N>
__device__ __forceinline__ void cp_wait() {
    asm volatile("cp.async.wait_group %0;" :: "n"(N) : "memory");
}
#define LDSM_X4(r0, r1, r2, r3, addr)                                            \
    asm volatile("ldmatrix.sync.aligned.m8n8.x4.shared.b16 {%0,%1,%2,%3}, [%4];" \
                 : "=r"(r0), "=r"(r1), "=r"(r2), "=r"(r3) : "r"(addr))
#define MMA_BF16(d0, d1, d2, d3, a0, a1, a2, a3, b0, b1)                         \
    asm volatile("mma.sync.aligned.m16n8k16.row.col.f32.bf16.bf16.f32 "          \
                 "{%0,%1,%2,%3}, {%4,%5,%6,%7}, {%8,%9}, {%0,%1,%2,%3};"         \
                 : "+f"(d0), "+f"(d1), "+f"(d2), "+f"(d3)                        \
                 : "r"(a0), "r"(a1), "r"(a2), "r"(a3), "r"(b0), "r"(b1))
#define MMA4(Cn, a0, a1, a2, a3, b0, b1)                                         \
    MMA_BF16(Cn##_0, Cn##_1, Cn##_2, Cn##_3, a0, a1, a2, a3, b0, b1)
#define BF16SPLIT(v, hi, lo)                                                     \
    { hi = __float2bfloat16(v); lo = __float2bfloat16((v) - __bfloat162float(hi)); }

__device__ __forceinline__ float sigmoidf_(float x) {
    return 1.0f / (1.0f + expf(-x));
}

// N permutation for the gates GEMM (thread-local i/f/o/u grouping):
// n = q*256 + idx; blk = idx>>5; lh = idx&31
// n' = blk*128 + (lh>>4)*64 + (q + 4*((lh>>3)&1))*8 + (lh&7)
__device__ __forceinline__ int perm_n(int n) {
    int q = n >> 8, idx = n & 255;
    int lh = idx & 31;
    return (idx >> 5) * 128 + (lh >> 4) * 64 + ((q + 4 * ((lh >> 3) & 1)) << 3) +
           (lh & 7);
}

// ---------------------------------------------------------------- gbias (permuted)
__global__ void gbias_kernel(const float* __restrict__ g,
                             const float* __restrict__ V,
                             const float* __restrict__ Vb) {
    __shared__ float gs[HH];
    int b = blockIdx.x, t = threadIdx.x;
    gs[t] = g[b * HH + t];
    __syncthreads();
    int n = blockIdx.y * 256 + t;
    float acc = Vb[n];
    #pragma unroll 4
    for (int k = 0; k < HH; ++k) acc += gs[k] * V[k * G4 + n];
    g_gbias[b * G4 + perm_n(n)] = acc;
}

// ---------------------------------------------------------------- converts
__global__ void conv_A(const float* __restrict__ h, const float* __restrict__ x) {
    int t = blockIdx.x * 256 + threadIdx.x;   // MM*128 threads
    int m = t >> 7;
    int c = (t & 127) * 4;                    // 0..508
    const float* src = (c < 256) ? (h + (size_t)m * HH + c)
                                 : (x + (size_t)m * HH + (c - 256));
    float4 v = *(const float4*)src;
    size_t o = (size_t)m * K2 + c;
    __nv_bfloat16 h0, l0, h1, l1, h2, l2, h3, l3;
    BF16SPLIT(v.x, h0, l0); BF16SPLIT(v.y, h1, l1);
    BF16SPLIT(v.z, h2, l2); BF16SPLIT(v.w, h3, l3);
    *(__nv_bfloat162*)(g_A2hi + o)     = __halves2bfloat162(h0, h1);
    *(__nv_bfloat162*)(g_A2hi + o + 2) = __halves2bfloat162(h2, h3);
    *(__nv_bfloat162*)(g_A2lo + o)     = __halves2bfloat162(l0, l1);
    *(__nv_bfloat162*)(g_A2lo + o + 2) = __halves2bfloat162(l2, l3);
}

__global__ void conv_B(const float* __restrict__ Wh, const float* __restrict__ U,
                       const float* __restrict__ Wn, const float* __restrict__ Wn_a) {
    int t = blockIdx.x * 256 + threadIdx.x;
    if (t < G4 * K2) {
        int k = t >> 10, n = t & 1023;
        float v = (k < 256) ? Wh[(size_t)k * G4 + n]
                : (k < 512) ? U[(size_t)(k - 256) * G4 + n]
                            : Wn[(size_t)(k - 512) * G4 + n];
        __nv_bfloat16 hi, lo;
        BF16SPLIT(v, hi, lo);
        size_t np = (size_t)perm_n(n);
        g_B2hi[np * K2 + k] = hi;
        g_B2lo[np * K2 + k] = lo;
    } else {
        int t2 = t - G4 * K2;
        if (t2 < HH * HH) {
            int k = t2 >> 8, n = t2 & 255;
            float v = Wn_a[k * HH + n];
            __nv_bfloat16 hi, lo;
            BF16SPLIT(v, hi, lo);
            g_B1hi[n * HH + k] = hi;
            g_B1lo[n * HH + k] = lo;
        }
    }
}

// ---------------------------------------------------------------- gather
__global__ void gather_kernel(const float* __restrict__ h,
                              const int* __restrict__ idx,
                              const int* __restrict__ mask) {
    int tid = blockIdx.x * blockDim.x + threadIdx.x;
    int token = tid >> 6;
    int lane = tid & 63;
    if (token >= MM) return;
    int b = token >> 11;
    const int* ip = idx + token * NNB;
    const int* mp = mask + token * NNB;
    const float* hb = h + (size_t)b * SS * HH;
    float4 acc = make_float4(0.f, 0.f, 0.f, 0.f);
    #pragma unroll
    for (int n = 0; n < NNB; ++n) {
        int id = ip[n];
        int mk = mp[n];
        if (mk != 0 && id > 0) {
            const float4 v = *(const float4*)(hb + (size_t)(id - 1) * HH + lane * 4);
            acc.x += v.x; acc.y += v.y; acc.z += v.z; acc.w += v.w;
        }
    }
    size_t o = (size_t)token * HH + lane * 4;
    __nv_bfloat16 h0, l0, h1, l1, h2, l2, h3, l3;
    BF16SPLIT(acc.x, h0, l0); BF16SPLIT(acc.y, h1, l1);
    BF16SPLIT(acc.z, h2, l2); BF16SPLIT(acc.w, h3, l3);
    *(__nv_bfloat162*)(g_AGhi + o)     = __halves2bfloat162(h0, h1);
    *(__nv_bfloat162*)(g_AGhi + o + 2) = __halves2bfloat162(h2, h3);
    *(__nv_bfloat162*)(g_AGlo + o)     = __halves2bfloat162(l0, l1);
    *(__nv_bfloat162*)(g_AGlo + o + 2) = __halves2bfloat162(l2, l3);
}

// ---------------------------------------------------------------- mma GEMM
// 128x128 block, 8 warps (32m x 64n per warp), BK=16, THREE-stage cp.async
// pipeline (one __syncthreads per chunk), static 48 KB smem, split-bf16:
// C = Ahi*Bhi + Alo*Bhi + Ahi*Blo.
// Per stage: Ahi(+0) Alo(+4K) Bhi(+8K) Blo(+12K), 128 rows x 32 B,
// swizzle: off = row*32 + (kb ^ ((row&4)<<2)).
#define STG_B 16384

#define DECL4(p) float p##_0 = 0.f, p##_1 = 0.f, p##_2 = 0.f, p##_3 = 0.f

#define BJ_BLOCK(bj, CA0, CA1, CB0, CB1)                                       \
    do {                                                                       \
        int rowb = wn * 64 + (bj) * 16 + (lid & 15);                           \
        uint32_t offb = SB + 8192 + rowb * 32 + (KB ^ ((rowb & 4) << 2));      \
        uint32_t bh0, bh1, bh2, bh3, bl0, bl1, bl2, bl3;                       \
        LDSM_X4(bh0, bh1, bh2, bh3, offb);                                     \
        LDSM_X4(bl0, bl1, bl2, bl3, offb + 4096);                              \
        MMA4(CA0, ah0_0, ah0_1, ah0_2, ah0_3, bh0, bh2);                       \
        MMA4(CA1, ah0_0, ah0_1, ah0_2, ah0_3, bh1, bh3);                       \
        MMA4(CB0, ah1_0, ah1_1, ah1_2, ah1_3, bh0, bh2);                       \
        MMA4(CB1, ah1_0, ah1_1, ah1_2, ah1_3, bh1, bh3);                       \
        MMA4(CA0, al0_0, al0_1, al0_2, al0_3, bh0, bh2);                       \
        MMA4(CA1, al0_0, al0_1, al0_2, al0_3, bh1, bh3);                       \
        MMA4(CB0, al1_0, al1_1, al1_2, al1_3, bh0, bh2);                       \
        MMA4(CB1, al1_0, al1_1, al1_2, al1_3, bh1, bh3);                       \
        MMA4(CA0, ah0_0, ah0_1, ah0_2, ah0_3, bl0, bl2);                       \
        MMA4(CA1, ah0_0, ah0_1, ah0_2, ah0_3, bl1, bl3);                       \
        MMA4(CB0, ah1_0, ah1_1, ah1_2, ah1_3, bl0, bl2);                       \
        MMA4(CB1, ah1_0, ah1_1, ah1_2, ah1_3, bl1, bl3);                       \
    } while (0)

#define HN_ST(Cn, MI, NI)                                                      \
    do {                                                                       \
        int col = bn + wn * 64 + (NI) * 8 + tq * 2;                            \
        int m0 = bm + wm * 32 + (MI) * 16 + quad;                              \
        __nv_bfloat16 p0, q0, p1, q1;                                          \
        float v0 = Cn##_0 * 0.0625f, v1 = Cn##_1 * 0.0625f;                    \
        BF16SPLIT(v0, p0, q0); BF16SPLIT(v1, p1, q1);                          \
        size_t o = (size_t)m0 * K2 + 512 + col;                                \
        *(__nv_bfloat162*)(g_A2hi + o) = __halves2bfloat162(p0, p1);           \
        *(__nv_bfloat162*)(g_A2lo + o) = __halves2bfloat162(q0, q1);           \
        v0 = Cn##_2 * 0.0625f; v1 = Cn##_3 * 0.0625f;                          \
        BF16SPLIT(v0, p0, q0); BF16SPLIT(v1, p1, q1);                          \
        o = (size_t)(m0 + 8) * K2 + 512 + col;                                 \
        *(__nv_bfloat162*)(g_A2hi + o) = __halves2bfloat162(p0, p1);           \
        *(__nv_bfloat162*)(g_A2lo + o) = __halves2bfloat162(q0, q1);           \
    } while (0)

#define LSTM_E(i0, i1, f0, f1, o0, o1, u0, u1, MME, HCE, gI, gF, gO, gU)       \
    do {                                                                       \
        float2 cv = *(const float2*)(cin + (size_t)(MME) * HH + (HCE));        \
        float ivx = (i0) + gI.x, ivy = (i1) + gI.y;                            \
        float fvx = (f0) + gF.x, fvy = (f1) + gF.y;                            \
        float ovx = (o0) + gO.x, ovy = (o1) + gO.y;                            \
        float uvx = (u0) + gU.x, uvy = (u1) + gU.y;                            \
        float ncx = sigmoidf_(fvx) * cv.x + sigmoidf_(ivx) * tanhf(uvx);       \
        float ncy = sigmoidf_(fvy) * cv.y + sigmoidf_(ivy) * tanhf(uvy);       \
        float2 nh = make_float2(sigmoidf_(ovx) * tanhf(ncx),                   \
                                sigmoidf_(ovy) * tanhf(ncy));                  \
        *(float2*)(out + (size_t)(MME) * HH + (HCE)) = nh;                     \
        *(float2*)(out + (size_t)MM * HH + (size_t)(MME) * HH + (HCE)) =       \
            make_float2(ncx, ncy);                                             \
    } while (0)

// MODE0: hn = agg @ Wn_a^T / 16 -> A2 cols 512..767 (bf16 hi/lo), KTOT=256
// MODE1: gates(perm cols) + gbias -> fused LSTM -> out, KTOT=768
// All scratch operand pointers bound INSIDE device code.
template <int MODE>
__global__ __launch_bounds__(256, 2)
void mma_gemm(const float* __restrict__ cin, float* __restrict__ out) {
    constexpr int KTOT = (MODE == 0) ? HH : K2;
    constexpr int NC = KTOT / 16;

    const __nv_bfloat16* __restrict__ A_hi = (MODE == 0) ? g_AGhi : g_A2hi;
    const __nv_bfloat16* __restrict__ A_lo = (MODE == 0) ? g_AGlo : g_A2lo;
    const __nv_bfloat16* __restrict__ B_hi = (MODE == 0) ? g_B1hi : g_B2hi;
    const __nv_bfloat16* __restrict__ B_lo = (MODE == 0) ? g_B1lo : g_B2lo;

    __shared__ __align__(128) char smem_buf[3 * STG_B];   // 48 KB static
    const uint32_t sb = smem_u32(smem_buf);
    const int tid = threadIdx.x;
    const int wid = tid >> 5, lid = tid & 31;
    const int wm = wid & 3, wn = wid >> 2;       // 4 x 2 warp grid
    const int bm = blockIdx.y * 128, bn = blockIdx.x * 128;

    DECL4(C00); DECL4(C01); DECL4(C02); DECL4(C03);
    DECL4(C04); DECL4(C05); DECL4(C06); DECL4(C07);
    DECL4(C10); DECL4(C11); DECL4(C12); DECL4(C13);
    DECL4(C14); DECL4(C15); DECL4(C16); DECL4(C17);

    // stage loader (device-side pointers only)
    const int lrow = tid >> 1;
    const uint32_t loff = (uint32_t)lrow * 32 +
                          (((uint32_t)(tid & 1) * 16) ^ ((lrow & 4) << 2));
    const int le8 = (tid & 1) * 8;

#define LOAD_STAGE(st, kc)                                                     \
    {                                                                          \
        const int k0_ = (kc) * 16;                                             \
        const uint32_t base_ = sb + (uint32_t)(st) * STG_B + loff;             \
        const size_t ga_ = (size_t)(bm + lrow) * KTOT + k0_ + le8;             \
        const size_t gb_ = (size_t)(bn + lrow) * KTOT + k0_ + le8;             \
        cp_async16(base_, A_hi + ga_);                                         \
        cp_async16(base_ + 4096, A_lo + ga_);                                  \
        cp_async16(base_ + 8192, B_hi + gb_);                                  \
        cp_async16(base_ + 12288, B_lo + gb_);                                 \
    }

    // 3-stage prologue: stages 0 and 1 in flight
    LOAD_STAGE(0, 0);
    cp_commit();
    LOAD_STAGE(1, 1);
    cp_commit();

    int s_cur = 0;   // stage buffer for chunk kc
    int s_nxt = 2;   // stage buffer for chunk kc+2

    #pragma unroll 1
    for (int kc = 0; kc < NC; ++kc) {
        cp_wait<1>();          // chunk kc landed (kc+1 may still be in flight)
        __syncthreads();       // also: all warps done reading buffer s_nxt
        if (kc + 2 < NC) LOAD_STAGE(s_nxt, kc + 2);
        cp_commit();           // keep group accounting uniform (empty ok)

        const uint32_t SB = sb + (uint32_t)s_cur * STG_B;
        const uint32_t KB = (uint32_t)(lid >> 4) * 16;

        uint32_t ah0_0, ah0_1, ah0_2, ah0_3, ah1_0, ah1_1, ah1_2, ah1_3;
        uint32_t al0_0, al0_1, al0_2, al0_3, al1_0, al1_1, al1_2, al1_3;
        {
            int rowa = wm * 32 + (lid & 15);
            uint32_t offa = SB + rowa * 32 + (KB ^ ((rowa & 4) << 2));
            LDSM_X4(ah0_0, ah0_1, ah0_2, ah0_3, offa);
            LDSM_X4(al0_0, al0_1, al0_2, al0_3, offa + 4096);
            int rowc = rowa + 16;
            uint32_t offc = SB + rowc * 32 + (KB ^ ((rowc & 4) << 2));
            LDSM_X4(ah1_0, ah1_1, ah1_2, ah1_3, offc);
            LDSM_X4(al1_0, al1_1, al1_2, al1_3, offc + 4096);
        }
        BJ_BLOCK(0, C00, C01, C10, C11);
        BJ_BLOCK(1, C02, C03, C12, C13);
        BJ_BLOCK(2, C04, C05, C14, C15);
        BJ_BLOCK(3, C06, C07, C16, C17);

        s_cur = (s_cur == 2) ? 0 : s_cur + 1;
        s_nxt = (s_nxt == 2) ? 0 : s_nxt + 1;
    }
#undef LOAD_STAGE

    // Ensure accumulators are final before epilogue overwrites smem-independent
    // outputs; also separates last compute from any lingering reads.
    __syncthreads();

    // -------- epilogue --------
    const int quad = lid >> 2, tq = lid & 3;

    if (MODE == 0) {
        HN_ST(C00, 0, 0); HN_ST(C01, 0, 1); HN_ST(C02, 0, 2); HN_ST(C03, 0, 3);
        HN_ST(C04, 0, 4); HN_ST(C05, 0, 5); HN_ST(C06, 0, 6); HN_ST(C07, 0, 7);
        HN_ST(C10, 1, 0); HN_ST(C11, 1, 1); HN_ST(C12, 1, 2); HN_ST(C13, 1, 3);
        HN_ST(C14, 1, 4); HN_ST(C15, 1, 5); HN_ST(C16, 1, 6); HN_ST(C17, 1, 7);
    } else {
        const int bi = blockIdx.y >> 4;          // batch (16 m-tiles per batch)
        const float* gbp = g_gbias + bi * G4 + blockIdx.x * 128 + wn * 64 + tq * 2;
        float2 gI0 = *(const float2*)(gbp + 0);
        float2 gF0 = *(const float2*)(gbp + 8);
        float2 gO0 = *(const float2*)(gbp + 16);
        float2 gU0 = *(const float2*)(gbp + 24);
        float2 gI1 = *(const float2*)(gbp + 32);
        float2 gF1 = *(const float2*)(gbp + 40);
        float2 gO1 = *(const float2*)(gbp + 48);
        float2 gU1 = *(const float2*)(gbp + 56);
        const int m0 = bm + wm * 32 + quad;
        const int hc0 = blockIdx.x * 32 + wn * 16 + tq * 2;
        const int hc1 = hc0 + 8;
        // mi=0
        LSTM_E(C00_0, C00_1, C01_0, C01_1, C02_0, C02_1, C03_0, C03_1,
               m0, hc0, gI0, gF0, gO0, gU0);
        LSTM_E(C00_2, C00_3, C01_2, C01_3, C02_2, C02_3, C03_2, C03_3,
               m0 + 8, hc0, gI0, gF0, gO0, gU0);
        LSTM_E(C04_0, C04_1, C05_0, C05_1, C06_0, C06_1, C07_0, C07_1,
               m0, hc1, gI1, gF1, gO1, gU1);
        LSTM_E(C04_2, C04_3, C05_2, C05_3, C06_2, C06_3, C07_2, C07_3,
               m0 + 8, hc1, gI1, gF1, gO1, gU1);
        // mi=1
        LSTM_E(C10_0, C10_1, C11_0, C11_1, C12_0, C12_1, C13_0, C13_1,
               m0 + 16, hc0, gI0, gF0, gO0, gU0);
        LSTM_E(C10_2, C10_3, C11_2, C11_3, C12_2, C12_3, C13_2, C13_3,
               m0 + 24, hc0, gI0, gF0, gO0, gU0);
        LSTM_E(C14_0, C14_1, C15_0, C15_1, C16_0, C16_1, C17_0, C17_1,
               m0 + 16, hc1, gI1, gF1, gO1, gU1);
        LSTM_E(C14_2, C14_3, C15_2, C15_3, C16_2, C16_3, C17_2, C17_3,
               m0 + 24, hc1, gI1, gF1, gO1, gU1);
    }
}

// ----------------------------------------------------------------------------
extern "C" void kernel_launch(void* const* d_in, const int* in_sizes, int n_in,
                              void* d_out, int out_size) {
    const float* x    = (const float*)d_in[0];
    const float* h    = (const float*)d_in[1];
    const float* c    = (const float*)d_in[2];
    const float* g    = (const float*)d_in[3];
    const int*   idx  = (const int*)d_in[4];
    const int*   mask = (const int*)d_in[5];
    // d_in[6] Wh_a, d_in[8..12]: unused — softmax over logits*1e-25 is exactly
    // uniform in fp32, so the attention score is 1/16 for every neighbor.
    const float* Wn_a = (const float*)d_in[7];
    const float* Wh   = (const float*)d_in[13];
    const float* Wn   = (const float*)d_in[14];
    const float* U    = (const float*)d_in[15];
    const float* V    = (const float*)d_in[16];
    const float* Vb   = (const float*)d_in[17];
    float* out = (float*)d_out;

    gbias_kernel<<<dim3(BB, 4), 256>>>(g, V, Vb);
    conv_A<<<(MM * 128) / 256, 256>>>(h, x);
    conv_B<<<(G4 * K2 + HH * HH + 255) / 256, 256>>>(Wh, U, Wn, Wn_a);
    gather_kernel<<<(MM * 64) / 256, 256>>>(h, idx, mask);
    // hn = agg @ Wn_a^T-layout / 16   (M=16384, N=256, K=256)
    mma_gemm<0><<<dim3(2, MM / 128), 256>>>(nullptr, nullptr);
    // gates(+fused LSTM) -> out       (M=16384, N=1024 permuted, K=768)
    mma_gemm<1><<<dim3(8, MM / 128), 256>>>(c, out);
}

// round 15
// speedup vs baseline: 4.3895x; 1.9579x over previous
#include <cuda_runtime.h>
#include <cuda_fp16.h>
#include <cstdint>
#include <math.h>

// ---------------------------------------------------------------- constants
#define BB 8
#define SS 2048
#define NNB 16
#define HH 256
#define MM (BB * SS)          // 16384 tokens
#define G4 (4 * HH)           // 1024
#define K2 768                // fused K for gates GEMM

// -------- scratch: device globals, referenced ONLY from device code --------
__device__ float g_gbias[BB * G4];                  // permuted layout
__device__ __half g_A2[(size_t)MM * K2];            // [h | x | hn] fp16  24 MB
__device__ __half g_B2[G4 * K2];                    // perm([Wh;U;Wn]^T)  1.5 MB
__device__ __half g_B1[HH * HH];                    // Wn_a^T (n-major)
__device__ __half g_AG[(size_t)MM * HH];            // neighbor agg       8 MB

// ---------------------------------------------------------------- PTX utils
__device__ __forceinline__ uint32_t smem_u32(const void* p) {
    uint32_t a;
    asm("{ .reg .u64 t; cvta.to.shared.u64 t, %1; cvt.u32.u64 %0, t; }"
        : "=r"(a) : "l"(p));
    return a;
}
__device__ __forceinline__ void cp_async16(uint32_t dst, const void* src) {
    asm volatile("cp.async.cg.shared.global [%0], [%1], 16;"
                 :: "r"(dst), "l"(src) : "memory");
}
__device__ __forceinline__ void cp_commit() {
    asm volatile("cp.async.commit_group;" ::: "memory");
}
template <int N>
__device__ __forceinline__ void cp_wait() {
    asm volatile("cp.async.wait_group %0;" :: "n"(N) : "memory");
}
#define LDSM_X4(r0, r1, r2, r3, addr)                                            \
    asm volatile("ldmatrix.sync.aligned.m8n8.x4.shared.b16 {%0,%1,%2,%3}, [%4];" \
                 : "=r"(r0), "=r"(r1), "=r"(r2), "=r"(r3) : "r"(addr))
#define MMA_F16(d0, d1, d2, d3, a0, a1, a2, a3, b0, b1)                          \
    asm volatile("mma.sync.aligned.m16n8k16.row.col.f32.f16.f16.f32 "            \
                 "{%0,%1,%2,%3}, {%4,%5,%6,%7}, {%8,%9}, {%0,%1,%2,%3};"         \
                 : "+f"(d0), "+f"(d1), "+f"(d2), "+f"(d3)                        \
                 : "r"(a0), "r"(a1), "r"(a2), "r"(a3), "r"(b0), "r"(b1))
#define MMA4(Cn, a0, a1, a2, a3, b0, b1)                                         \
    MMA_F16(Cn##_0, Cn##_1, Cn##_2, Cn##_3, a0, a1, a2, a3, b0, b1)

__device__ __forceinline__ float sigmoidf_(float x) {
    return 1.0f / (1.0f + expf(-x));
}

// N permutation for the gates GEMM (thread-local i/f/o/u grouping):
// n = q*256 + idx; blk = idx>>5; lh = idx&31
// n' = blk*128 + (lh>>4)*64 + (q + 4*((lh>>3)&1))*8 + (lh&7)
__device__ __forceinline__ int perm_n(int n) {
    int q = n >> 8, idx = n & 255;
    int lh = idx & 31;
    return (idx >> 5) * 128 + (lh >> 4) * 64 + ((q + 4 * ((lh >> 3) & 1)) << 3) +
           (lh & 7);
}

// ---------------------------------------------------------------- gbias (permuted)
__global__ void gbias_kernel(const float* __restrict__ g,
                             const float* __restrict__ V,
                             const float* __restrict__ Vb) {
    __shared__ float gs[HH];
    int b = blockIdx.x, t = threadIdx.x;
    gs[t] = g[b * HH + t];
    __syncthreads();
    int n = blockIdx.y * 256 + t;
    float acc = Vb[n];
    #pragma unroll 4
    for (int k = 0; k < HH; ++k) acc += gs[k] * V[k * G4 + n];
    g_gbias[b * G4 + perm_n(n)] = acc;
}

// ---------------------------------------------------------------- converts
__global__ void conv_A(const float* __restrict__ h, const float* __restrict__ x) {
    int t = blockIdx.x * 256 + threadIdx.x;   // MM*128 threads
    int m = t >> 7;
    int c = (t & 127) * 4;                    // 0..508
    const float* src = (c < 256) ? (h + (size_t)m * HH + c)
                                 : (x + (size_t)m * HH + (c - 256));
    float4 v = *(const float4*)src;
    size_t o = (size_t)m * K2 + c;
    *(__half2*)(g_A2 + o)     = __floats2half2_rn(v.x, v.y);
    *(__half2*)(g_A2 + o + 2) = __floats2half2_rn(v.z, v.w);
}

__global__ void conv_B(const float* __restrict__ Wh, const float* __restrict__ U,
                       const float* __restrict__ Wn, const float* __restrict__ Wn_a) {
    int t = blockIdx.x * 256 + threadIdx.x;
    if (t < G4 * K2) {
        int k = t >> 10, n = t & 1023;
        float v = (k < 256) ? Wh[(size_t)k * G4 + n]
                : (k < 512) ? U[(size_t)(k - 256) * G4 + n]
                            : Wn[(size_t)(k - 512) * G4 + n];
        g_B2[(size_t)perm_n(n) * K2 + k] = __float2half_rn(v);
    } else {
        int t2 = t - G4 * K2;
        if (t2 < HH * HH) {
            int k = t2 >> 8, n = t2 & 255;
            g_B1[n * HH + k] = __float2half_rn(Wn_a[k * HH + n]);
        }
    }
}

// ---------------------------------------------------------------- gather
__global__ void gather_kernel(const float* __restrict__ h,
                              const int* __restrict__ idx,
                              const int* __restrict__ mask) {
    int tid = blockIdx.x * blockDim.x + threadIdx.x;
    int token = tid >> 6;
    int lane = tid & 63;
    if (token >= MM) return;
    int b = token >> 11;
    const int* ip = idx + token * NNB;
    const int* mp = mask + token * NNB;
    const float* hb = h + (size_t)b * SS * HH;
    float4 acc = make_float4(0.f, 0.f, 0.f, 0.f);
    #pragma unroll
    for (int n = 0; n < NNB; ++n) {
        int id = ip[n];
        int mk = mp[n];
        if (mk != 0 && id > 0) {
            const float4 v = *(const float4*)(hb + (size_t)(id - 1) * HH + lane * 4);
            acc.x += v.x; acc.y += v.y; acc.z += v.z; acc.w += v.w;
        }
    }
    size_t o = (size_t)token * HH + lane * 4;
    *(__half2*)(g_AG + o)     = __floats2half2_rn(acc.x, acc.y);
    *(__half2*)(g_AG + o + 2) = __floats2half2_rn(acc.z, acc.w);
}

// ---------------------------------------------------------------- mma GEMM
// 128x128 block, 8 warps (32m x 64n per warp), BK=16, THREE-stage cp.async
// pipeline (one __syncthreads per chunk), static 24 KB smem, fp16 single-pass
// (fp16's 11 mantissa bits give ~2^-11 input rounding; fp32 accumulate).
// Per stage: A(+0) B(+4K), 128 rows x 32 B,
// swizzle: off = row*32 + (kb ^ ((row&4)<<2)).
#define STG_B 8192

#define DECL4(p) float p##_0 = 0.f, p##_1 = 0.f, p##_2 = 0.f, p##_3 = 0.f

#define BJ_BLOCK(bj, CA0, CA1, CB0, CB1)                                       \
    do {                                                                       \
        int rowb = wn * 64 + (bj) * 16 + (lid & 15);                           \
        uint32_t offb = SB + 4096 + rowb * 32 + (KB ^ ((rowb & 4) << 2));      \
        uint32_t bh0, bh1, bh2, bh3;                                           \
        LDSM_X4(bh0, bh1, bh2, bh3, offb);                                     \
        MMA4(CA0, ah0_0, ah0_1, ah0_2, ah0_3, bh0, bh2);                       \
        MMA4(CA1, ah0_0, ah0_1, ah0_2, ah0_3, bh1, bh3);                       \
        MMA4(CB0, ah1_0, ah1_1, ah1_2, ah1_3, bh0, bh2);                       \
        MMA4(CB1, ah1_0, ah1_1, ah1_2, ah1_3, bh1, bh3);                       \
    } while (0)

#define HN_ST(Cn, MI, NI)                                                      \
    do {                                                                       \
        int col = bn + wn * 64 + (NI) * 8 + tq * 2;                            \
        int m0 = bm + wm * 32 + (MI) * 16 + quad;                              \
        size_t o = (size_t)m0 * K2 + 512 + col;                                \
        *(__half2*)(g_A2 + o) =                                                \
            __floats2half2_rn(Cn##_0 * 0.0625f, Cn##_1 * 0.0625f);             \
        o = (size_t)(m0 + 8) * K2 + 512 + col;                                 \
        *(__half2*)(g_A2 + o) =                                                \
            __floats2half2_rn(Cn##_2 * 0.0625f, Cn##_3 * 0.0625f);             \
    } while (0)

#define LSTM_E(i0, i1, f0, f1, o0, o1, u0, u1, MME, HCE, gI, gF, gO, gU)       \
    do {                                                                       \
        float2 cv = *(const float2*)(cin + (size_t)(MME) * HH + (HCE));        \
        float ivx = (i0) + gI.x, ivy = (i1) + gI.y;                            \
        float fvx = (f0) + gF.x, fvy = (f1) + gF.y;                            \
        float ovx = (o0) + gO.x, ovy = (o1) + gO.y;                            \
        float uvx = (u0) + gU.x, uvy = (u1) + gU.y;                            \
        float ncx = sigmoidf_(fvx) * cv.x + sigmoidf_(ivx) * tanhf(uvx);       \
        float ncy = sigmoidf_(fvy) * cv.y + sigmoidf_(ivy) * tanhf(uvy);       \
        float2 nh = make_float2(sigmoidf_(ovx) * tanhf(ncx),                   \
                                sigmoidf_(ovy) * tanhf(ncy));                  \
        *(float2*)(out + (size_t)(MME) * HH + (HCE)) = nh;                     \
        *(float2*)(out + (size_t)MM * HH + (size_t)(MME) * HH + (HCE)) =       \
            make_float2(ncx, ncy);                                             \
    } while (0)

// MODE0: hn = agg @ Wn_a^T / 16 -> A2 cols 512..767 (fp16), KTOT=256
// MODE1: gates(perm cols) + gbias -> fused LSTM -> out, KTOT=768
// All scratch operand pointers bound INSIDE device code.
template <int MODE>
__global__ __launch_bounds__(256, 2)
void mma_gemm(const float* __restrict__ cin, float* __restrict__ out) {
    constexpr int KTOT = (MODE == 0) ? HH : K2;
    constexpr int NC = KTOT / 16;

    const __half* __restrict__ A = (MODE == 0) ? g_AG : g_A2;
    const __half* __restrict__ B = (MODE == 0) ? g_B1 : g_B2;

    __shared__ __align__(128) char smem_buf[3 * STG_B];   // 24 KB static
    const uint32_t sb = smem_u32(smem_buf);
    const int tid = threadIdx.x;
    const int wid = tid >> 5, lid = tid & 31;
    const int wm = wid & 3, wn = wid >> 2;       // 4 x 2 warp grid
    const int bm = blockIdx.y * 128, bn = blockIdx.x * 128;

    DECL4(C00); DECL4(C01); DECL4(C02); DECL4(C03);
    DECL4(C04); DECL4(C05); DECL4(C06); DECL4(C07);
    DECL4(C10); DECL4(C11); DECL4(C12); DECL4(C13);
    DECL4(C14); DECL4(C15); DECL4(C16); DECL4(C17);

    // stage loader (device-side pointers only): one 16B cp.async per tile
    const int lrow = tid >> 1;                   // 0..127
    const uint32_t loff = (uint32_t)lrow * 32 +
                          (((uint32_t)(tid & 1) * 16) ^ ((lrow & 4) << 2));
    const int le8 = (tid & 1) * 8;               // 8 halves = 16 B

#define LOAD_STAGE(st, kc)                                                     \
    {                                                                          \
        const int k0_ = (kc) * 16;                                             \
        const uint32_t base_ = sb + (uint32_t)(st) * STG_B + loff;             \
        const size_t ga_ = (size_t)(bm + lrow) * KTOT + k0_ + le8;             \
        const size_t gb_ = (size_t)(bn + lrow) * KTOT + k0_ + le8;             \
        cp_async16(base_, A + ga_);                                            \
        cp_async16(base_ + 4096, B + gb_);                                     \
    }

    // 3-stage prologue: stages 0 and 1 in flight
    LOAD_STAGE(0, 0);
    cp_commit();
    LOAD_STAGE(1, 1);
    cp_commit();

    int s_cur = 0;   // stage buffer for chunk kc
    int s_nxt = 2;   // stage buffer for chunk kc+2

    #pragma unroll 1
    for (int kc = 0; kc < NC; ++kc) {
        cp_wait<1>();          // chunk kc landed (kc+1 may still be in flight)
        __syncthreads();       // all warps done reading buffer s_nxt
        if (kc + 2 < NC) LOAD_STAGE(s_nxt, kc + 2);
        cp_commit();           // keep group accounting uniform (empty ok)

        const uint32_t SB = sb + (uint32_t)s_cur * STG_B;
        const uint32_t KB = (uint32_t)(lid >> 4) * 16;

        uint32_t ah0_0, ah0_1, ah0_2, ah0_3, ah1_0, ah1_1, ah1_2, ah1_3;
        {
            int rowa = wm * 32 + (lid & 15);
            uint32_t offa = SB + rowa * 32 + (KB ^ ((rowa & 4) << 2));
            LDSM_X4(ah0_0, ah0_1, ah0_2, ah0_3, offa);
            int rowc = rowa + 16;
            uint32_t offc = SB + rowc * 32 + (KB ^ ((rowc & 4) << 2));
            LDSM_X4(ah1_0, ah1_1, ah1_2, ah1_3, offc);
        }
        BJ_BLOCK(0, C00, C01, C10, C11);
        BJ_BLOCK(1, C02, C03, C12, C13);
        BJ_BLOCK(2, C04, C05, C14, C15);
        BJ_BLOCK(3, C06, C07, C16, C17);

        s_cur = (s_cur == 2) ? 0 : s_cur + 1;
        s_nxt = (s_nxt == 2) ? 0 : s_nxt + 1;
    }
#undef LOAD_STAGE

    __syncthreads();

    // -------- epilogue --------
    const int quad = lid >> 2, tq = lid & 3;

    if (MODE == 0) {
        HN_ST(C00, 0, 0); HN_ST(C01, 0, 1); HN_ST(C02, 0, 2); HN_ST(C03, 0, 3);
        HN_ST(C04, 0, 4); HN_ST(C05, 0, 5); HN_ST(C06, 0, 6); HN_ST(C07, 0, 7);
        HN_ST(C10, 1, 0); HN_ST(C11, 1, 1); HN_ST(C12, 1, 2); HN_ST(C13, 1, 3);
        HN_ST(C14, 1, 4); HN_ST(C15, 1, 5); HN_ST(C16, 1, 6); HN_ST(C17, 1, 7);
    } else {
        const int bi = blockIdx.y >> 4;          // batch (16 m-tiles per batch)
        const float* gbp = g_gbias + bi * G4 + blockIdx.x * 128 + wn * 64 + tq * 2;
        float2 gI0 = *(const float2*)(gbp + 0);
        float2 gF0 = *(const float2*)(gbp + 8);
        float2 gO0 = *(const float2*)(gbp + 16);
        float2 gU0 = *(const float2*)(gbp + 24);
        float2 gI1 = *(const float2*)(gbp + 32);
        float2 gF1 = *(const float2*)(gbp + 40);
        float2 gO1 = *(const float2*)(gbp + 48);
        float2 gU1 = *(const float2*)(gbp + 56);
        const int m0 = bm + wm * 32 + quad;
        const int hc0 = blockIdx.x * 32 + wn * 16 + tq * 2;
        const int hc1 = hc0 + 8;
        // mi=0
        LSTM_E(C00_0, C00_1, C01_0, C01_1, C02_0, C02_1, C03_0, C03_1,
               m0, hc0, gI0, gF0, gO0, gU0);
        LSTM_E(C00_2, C00_3, C01_2, C01_3, C02_2, C02_3, C03_2, C03_3,
               m0 + 8, hc0, gI0, gF0, gO0, gU0);
        LSTM_E(C04_0, C04_1, C05_0, C05_1, C06_0, C06_1, C07_0, C07_1,
               m0, hc1, gI1, gF1, gO1, gU1);
        LSTM_E(C04_2, C04_3, C05_2, C05_3, C06_2, C06_3, C07_2, C07_3,
               m0 + 8, hc1, gI1, gF1, gO1, gU1);
        // mi=1
        LSTM_E(C10_0, C10_1, C11_0, C11_1, C12_0, C12_1, C13_0, C13_1,
               m0 + 16, hc0, gI0, gF0, gO0, gU0);
        LSTM_E(C10_2, C10_3, C11_2, C11_3, C12_2, C12_3, C13_2, C13_3,
               m0 + 24, hc0, gI0, gF0, gO0, gU0);
        LSTM_E(C14_0, C14_1, C15_0, C15_1, C16_0, C16_1, C17_0, C17_1,
               m0 + 16, hc1, gI1, gF1, gO1, gU1);
        LSTM_E(C14_2, C14_3, C15_2, C15_3, C16_2, C16_3, C17_2, C17_3,
               m0 + 24, hc1, gI1, gF1, gO1, gU1);
    }
}

// ----------------------------------------------------------------------------
extern "C" void kernel_launch(void* const* d_in, const int* in_sizes, int n_in,
                              void* d_out, int out_size) {
    const float* x    = (const float*)d_in[0];
    const float* h    = (const float*)d_in[1];
    const float* c    = (const float*)d_in[2];
    const float* g    = (const float*)d_in[3];
    const int*   idx  = (const int*)d_in[4];
    const int*   mask = (const int*)d_in[5];
    // d_in[6] Wh_a, d_in[8..12]: unused — softmax over logits*1e-25 is exactly
    // uniform in fp32, so the attention score is 1/16 for every neighbor.
    const float* Wn_a = (const float*)d_in[7];
    const float* Wh   = (const float*)d_in[13];
    const float* Wn   = (const float*)d_in[14];
    const float* U    = (const float*)d_in[15];
    const float* V    = (const float*)d_in[16];
    const float* Vb   = (const float*)d_in[17];
    float* out = (float*)d_out;

    gbias_kernel<<<dim3(BB, 4), 256>>>(g, V, Vb);
    conv_A<<<(MM * 128) / 256, 256>>>(h, x);
    conv_B<<<(G4 * K2 + HH * HH + 255) / 256, 256>>>(Wh, U, Wn, Wn_a);
    gather_kernel<<<(MM * 64) / 256, 256>>>(h, idx, mask);
    // hn = agg @ Wn_a^T-layout / 16   (M=16384, N=256, K=256)
    mma_gemm<0><<<dim3(2, MM / 128), 256>>>(nullptr, nullptr);
    // gates(+fused LSTM) -> out       (M=16384, N=1024 permuted, K=768)
    mma_gemm<1><<<dim3(8, MM / 128), 256>>>(c, out);
}